// round 3
// baseline (speedup 1.0000x reference)
#include <cuda_runtime.h>

// Problem constants
#define S_LEN   64
#define NBATCH  64
#define EMBD    512
#define HIDD    512
#define NVOCAB  10000
#define SB      4096            // S_LEN * NBATCH
#define LOGITS_SZ 40960000      // SB * NVOCAB
#define HFIN_SZ   65536         // 2 * NBATCH * HIDD

#define RSPLIT  4               // K-splits per recurrence step (128 k each)
#define RNTILE  16              // N-tiles of 32 cols each

// Scratch (device globals: no cudaMalloc allowed)
__device__ float g_A0[SB * HIDD];
__device__ float g_H0[SB * HIDD];
__device__ float g_A1[SB * HIDD];
__device__ float g_H1[SB * HIDD];
__device__ int   g_ctr[2 * S_LEN * RNTILE];

// ---------------------------------------------------------------------------
// Generic NT SGEMM:  C[M,N] = A(M,K) * B(N,K)^T + bias1[N] (+ bias2[N])
// A rows optionally gathered through tok[] (embedding lookup).
// Tiling: 128x128 per CTA, BK=16, 256 threads, 8x8 microtile.
// SMEM stored k-major with XOR-4 swizzle so transposed stores are cheap and
// LDS.128 reads stay conflict-free.
// ---------------------------------------------------------------------------
template <bool GATHER>
__global__ __launch_bounds__(256)
void sgemm_nt(const float* __restrict__ A, const int* __restrict__ tok,
              const float* __restrict__ B,
              const float* __restrict__ bias1, const float* __restrict__ bias2,
              float* __restrict__ C, int N, int K, int ldc)
{
    __shared__ float As[16 * 128];
    __shared__ float Bs[16 * 128];

    const int tid = threadIdx.x;
    const int m0  = blockIdx.y * 128;
    const int n0  = blockIdx.x * 128;
    const int tx  = tid & 15;
    const int ty  = tid >> 4;

    // load mapping: each thread loads 2 A rows + 2 B rows, 4 floats each
    const int row0 = tid >> 2;          // 0..63
    const int row1 = row0 + 64;         // 64..127
    const int kq   = (tid & 3) << 2;    // 0,4,8,12

    float4 aR0, aR1, bR0, bR1;

#define LOAD_TILES(K0_)                                                          \
    do {                                                                         \
        const float* pa0 = GATHER ? (A + (size_t)tok[m0 + row0] * K)             \
                                  : (A + (size_t)(m0 + row0) * K);               \
        const float* pa1 = GATHER ? (A + (size_t)tok[m0 + row1] * K)             \
                                  : (A + (size_t)(m0 + row1) * K);               \
        aR0 = *(const float4*)(pa0 + (K0_) + kq);                                \
        aR1 = *(const float4*)(pa1 + (K0_) + kq);                                \
        int gc0 = n0 + row0, gc1 = n0 + row1;                                    \
        bR0 = (gc0 < N) ? *(const float4*)(B + (size_t)gc0 * K + (K0_) + kq)     \
                        : make_float4(0.f, 0.f, 0.f, 0.f);                       \
        bR1 = (gc1 < N) ? *(const float4*)(B + (size_t)gc1 * K + (K0_) + kq)     \
                        : make_float4(0.f, 0.f, 0.f, 0.f);                       \
    } while (0)

    float acc[8][8];
#pragma unroll
    for (int i = 0; i < 8; ++i)
#pragma unroll
        for (int j = 0; j < 8; ++j) acc[i][j] = 0.f;

    LOAD_TILES(0);

    for (int k0 = 0; k0 < K; k0 += 16) {
        // transposed swizzled stores into SMEM (k-major, XOR-4 swizzle)
        {
            int ph = ((row0 >> 2) ^ (kq >> 2));
            int b  = kq * 128 + (ph << 2) + (row0 & 3);
            As[b] = aR0.x; As[b + 128] = aR0.y; As[b + 256] = aR0.z; As[b + 384] = aR0.w;
        }
        {
            int ph = ((row1 >> 2) ^ (kq >> 2));
            int b  = kq * 128 + (ph << 2) + (row1 & 3);
            As[b] = aR1.x; As[b + 128] = aR1.y; As[b + 256] = aR1.z; As[b + 384] = aR1.w;
        }
        {
            int ph = ((row0 >> 2) ^ (kq >> 2));
            int b  = kq * 128 + (ph << 2) + (row0 & 3);
            Bs[b] = bR0.x; Bs[b + 128] = bR0.y; Bs[b + 256] = bR0.z; Bs[b + 384] = bR0.w;
        }
        {
            int ph = ((row1 >> 2) ^ (kq >> 2));
            int b  = kq * 128 + (ph << 2) + (row1 & 3);
            Bs[b] = bR1.x; Bs[b + 128] = bR1.y; Bs[b + 256] = bR1.z; Bs[b + 384] = bR1.w;
        }
        __syncthreads();

        int kn = k0 + 16;
        if (kn < K) LOAD_TILES(kn);   // prefetch next chunk into registers

#pragma unroll
        for (int kk = 0; kk < 16; ++kk) {
            const int x = (kk >> 2);
            float4 a0 = *(const float4*)(As + kk * 128 + ((((ty << 1))     ^ x) << 2));
            float4 a1 = *(const float4*)(As + kk * 128 + ((((ty << 1) + 1) ^ x) << 2));
            float4 b0 = *(const float4*)(Bs + kk * 128 + ((((tx << 1))     ^ x) << 2));
            float4 b1 = *(const float4*)(Bs + kk * 128 + ((((tx << 1) + 1) ^ x) << 2));
            float av[8] = {a0.x, a0.y, a0.z, a0.w, a1.x, a1.y, a1.z, a1.w};
            float bv[8] = {b0.x, b0.y, b0.z, b0.w, b1.x, b1.y, b1.z, b1.w};
#pragma unroll
            for (int i = 0; i < 8; ++i)
#pragma unroll
                for (int j = 0; j < 8; ++j)
                    acc[i][j] = fmaf(av[i], bv[j], acc[i][j]);
        }
        __syncthreads();
    }
#undef LOAD_TILES

    // epilogue: bias add + store
    float badd[8];
#pragma unroll
    for (int j = 0; j < 8; ++j) {
        int c = n0 + (tx << 3) + j;
        float b = 0.f;
        if (c < N) {
            b = bias1[c];
            if (bias2) b += bias2[c];
        }
        badd[j] = b;
    }

    if (n0 + 128 <= N) {
#pragma unroll
        for (int i = 0; i < 8; ++i) {
            float* crow = C + (size_t)(m0 + (ty << 3) + i) * ldc + n0 + (tx << 3);
            float4 v0 = make_float4(acc[i][0] + badd[0], acc[i][1] + badd[1],
                                    acc[i][2] + badd[2], acc[i][3] + badd[3]);
            float4 v1 = make_float4(acc[i][4] + badd[4], acc[i][5] + badd[5],
                                    acc[i][6] + badd[6], acc[i][7] + badd[7]);
            *(float4*)(crow)     = v0;
            *(float4*)(crow + 4) = v1;
        }
    } else {
#pragma unroll
        for (int i = 0; i < 8; ++i) {
            float* crow = C + (size_t)(m0 + (ty << 3) + i) * ldc;
#pragma unroll
            for (int j = 0; j < 8; ++j) {
                int c = n0 + (tx << 3) + j;
                if (c < N) crow[c] = acc[i][j] + badd[j];
            }
        }
    }
}

// ---------------------------------------------------------------------------
// One recurrence step:  H[s] = tanh( Acc[s] += Hprev @ U^T )
// grid = (RNTILE=16 N-tiles of 32 cols, RSPLIT=4 K-splits of 128), 256 thr.
// Each CTA computes a 64x32 output block over a 128-wide K slice.
// Partials atomically added into the pre-biased accumulator rows; the last
// K-split CTA per N-tile (tracked via ctr) applies tanh and writes Hout.
// SMEM is exactly 48 KB; the completion flag is broadcast through Hs[0],
// which is dead after the compute loop (ordered by __syncthreads on both
// sides).
// ---------------------------------------------------------------------------
__global__ __launch_bounds__(256)
void rnn_step(const float* __restrict__ Hprev,   // [64,512]
              const float* __restrict__ U,       // [512,512]
              float* __restrict__ Acc,           // full A-buffer [4096,512]
              float* __restrict__ Hout,          // full H-buffer [4096,512]
              int* __restrict__ ctr, int s)
{
    // 64 rows x 128 k of H, 32 rows x 128 k of U  -> 48 KB total
    __shared__ float Hs[128 * 64];   // k-major, swizzled
    __shared__ float Us[128 * 32];   // k-major, swizzled

    const int tid = threadIdx.x;
    const int n0  = blockIdx.x * 32;       // output column tile (32 wide)
    const int k0  = blockIdx.y * 128;      // K slice (128 wide)
    // 256 threads, output 64x32=2048 -> 8 outputs/thread: 2 rows x 4 cols
    const int orow = (tid >> 3) << 1;      // 0..62 step 2
    const int ocol = (tid & 7) << 2;       // 0..28 step 4

    // ---- load H tile: 64 rows x 128 k = 8192 floats, 2048 float4 loads
#pragma unroll
    for (int l = 0; l < 8; ++l) {
        int idx = tid + l * 256;           // 0..2047
        int row = idx >> 5;                // 0..63
        int kq  = (idx & 31) << 2;         // 0..124
        float4 h = *(const float4*)(Hprev + (size_t)row * HIDD + k0 + kq);
        int ph = ((row >> 2) ^ (kq >> 2)) & 15;
        int b  = kq * 64 + (ph << 2) + (row & 3);
        Hs[b] = h.x; Hs[b + 64] = h.y; Hs[b + 128] = h.z; Hs[b + 192] = h.w;
    }
    // ---- load U tile: 32 rows x 128 k = 4096 floats, 1024 float4 loads
#pragma unroll
    for (int l = 0; l < 4; ++l) {
        int idx = tid + l * 256;           // 0..1023
        int row = idx >> 5;                // 0..31
        int kq  = (idx & 31) << 2;         // 0..124
        float4 u = *(const float4*)(U + (size_t)(n0 + row) * HIDD + k0 + kq);
        int ph = ((row >> 2) ^ (kq >> 2)) & 7;
        int b  = kq * 32 + (ph << 2) + (row & 3);
        Us[b] = u.x; Us[b + 32] = u.y; Us[b + 64] = u.z; Us[b + 96] = u.w;
    }
    __syncthreads();

    float acc[2][4];
#pragma unroll
    for (int i = 0; i < 2; ++i)
#pragma unroll
        for (int j = 0; j < 4; ++j) acc[i][j] = 0.f;

#pragma unroll 4
    for (int kk = 0; kk < 128; ++kk) {
        const int xh = (kk >> 2) & 15;
        const int xu = (kk >> 2) & 7;
        int r0 = orow, r1 = orow + 1;
        float a0 = Hs[kk * 64 + ((((r0 >> 2) ^ xh) & 15) << 2) + (r0 & 3)];
        float a1 = Hs[kk * 64 + ((((r1 >> 2) ^ xh) & 15) << 2) + (r1 & 3)];
        float4 b = *(const float4*)(Us + kk * 32 + ((((ocol >> 2) ^ xu) & 7) << 2));
        acc[0][0] = fmaf(a0, b.x, acc[0][0]);
        acc[0][1] = fmaf(a0, b.y, acc[0][1]);
        acc[0][2] = fmaf(a0, b.z, acc[0][2]);
        acc[0][3] = fmaf(a0, b.w, acc[0][3]);
        acc[1][0] = fmaf(a1, b.x, acc[1][0]);
        acc[1][1] = fmaf(a1, b.y, acc[1][1]);
        acc[1][2] = fmaf(a1, b.z, acc[1][2]);
        acc[1][3] = fmaf(a1, b.w, acc[1][3]);
    }

    // accumulate partials into the pre-biased Acc rows
#pragma unroll
    for (int i = 0; i < 2; ++i) {
        size_t rowoff = (size_t)(s * NBATCH + orow + i) * HIDD + n0 + ocol;
#pragma unroll
        for (int j = 0; j < 4; ++j)
            atomicAdd(Acc + rowoff + j, acc[i][j]);
    }
    __threadfence();
    __syncthreads();        // all partials of this CTA issued + Hs dead
    if (tid == 0)
        Hs[0] = (atomicAdd(&ctr[blockIdx.x], 1) == RSPLIT - 1) ? 1.f : 0.f;
    __syncthreads();

    if (Hs[0] != 0.f) {
        __threadfence();
        // 64 rows x 32 cols = 2048 elems
        for (int idx = tid; idx < 64 * 32; idx += 256) {
            int r = idx >> 5, c = idx & 31;
            size_t off = (size_t)(s * NBATCH + r) * HIDD + n0 + c;
            Hout[off] = tanhf(__ldcg(Acc + off));
        }
    }
}

__global__ void zero_ctr_kernel(int* __restrict__ ctr)
{
    int i = blockIdx.x * blockDim.x + threadIdx.x;
    if (i < 2 * S_LEN * RNTILE) ctr[i] = 0;
}

__global__ void finalize_kernel(const float* __restrict__ H0,
                                const float* __restrict__ H1,
                                float* __restrict__ out)
{
    int idx = blockIdx.x * blockDim.x + threadIdx.x;   // 0..65535
    float v;
    if (idx < NBATCH * HIDD)
        v = H0[(size_t)(S_LEN - 1) * NBATCH * HIDD + idx];
    else
        v = H1[(size_t)(S_LEN - 1) * NBATCH * HIDD + (idx - NBATCH * HIDD)];
    out[(size_t)LOGITS_SZ + idx] = v;
}

// ---------------------------------------------------------------------------
extern "C" void kernel_launch(void* const* d_in, const int* in_sizes, int n_in,
                              void* d_out, int out_size)
{
    const int*   tok    = (const int*)  d_in[0];
    const float* hidden = (const float*)d_in[1];
    const float* emb    = (const float*)d_in[2];
    const float* W0     = (const float*)d_in[3];
    const float* bW0    = (const float*)d_in[4];
    const float* W1     = (const float*)d_in[5];
    const float* bW1    = (const float*)d_in[6];
    const float* U0     = (const float*)d_in[7];
    const float* bU0    = (const float*)d_in[8];
    const float* U1     = (const float*)d_in[9];
    const float* bU1    = (const float*)d_in[10];
    const float* Wd     = (const float*)d_in[11];
    const float* bd     = (const float*)d_in[12];
    float* out = (float*)d_out;

    float *A0, *H0, *A1, *H1;
    int* ctr;
    cudaGetSymbolAddress((void**)&A0, g_A0);
    cudaGetSymbolAddress((void**)&H0, g_H0);
    cudaGetSymbolAddress((void**)&A1, g_A1);
    cudaGetSymbolAddress((void**)&H1, g_H1);
    cudaGetSymbolAddress((void**)&ctr, g_ctr);

    zero_ctr_kernel<<<8, 256>>>(ctr);

    // A0 = emb[tok] @ W0^T + bW0 + bU0   (M=4096, N=512, K=512)
    sgemm_nt<true><<<dim3(4, 32), 256>>>(emb, tok, W0, bW0, bU0, A0,
                                         HIDD, EMBD, HIDD);

    // layer-0 recurrence
    for (int s = 0; s < S_LEN; ++s) {
        const float* hp = s ? (H0 + (size_t)(s - 1) * NBATCH * HIDD) : hidden;
        rnn_step<<<dim3(RNTILE, RSPLIT), 256>>>(hp, U0, A0, H0,
                                                ctr + s * RNTILE, s);
    }

    // A1 = H0 @ W1^T + bW1 + bU1
    sgemm_nt<false><<<dim3(4, 32), 256>>>(H0, nullptr, W1, bW1, bU1, A1,
                                          HIDD, HIDD, HIDD);

    // layer-1 recurrence
    for (int s = 0; s < S_LEN; ++s) {
        const float* hp = s ? (H1 + (size_t)(s - 1) * NBATCH * HIDD)
                            : (hidden + NBATCH * HIDD);
        rnn_step<<<dim3(RNTILE, RSPLIT), 256>>>(hp, U1, A1, H1,
                                                ctr + (S_LEN + s) * RNTILE, s);
    }

    // logits = H1 @ Wd^T + bd   (M=4096, N=10000, K=512)
    sgemm_nt<false><<<dim3((NVOCAB + 127) / 128, 32), 256>>>(
        H1, nullptr, Wd, bd, nullptr, out, NVOCAB, HIDD, NVOCAB);

    // h_final
    if (out_size >= LOGITS_SZ + HFIN_SZ)
        finalize_kernel<<<HFIN_SZ / 256, 256>>>(H0, H1, out);
}